// round 1
// baseline (speedup 1.0000x reference)
#include <cuda_runtime.h>
#include <cuda_bf16.h>

#define D_MODEL 1024
#define NHEAD 16
#define DH 64
#define WIN 256
#define NB 2
#define NS 2048

// Scratch (allocation-free rule: __device__ globals)
__device__ float g_Q[NB * NHEAD * NS * DH];
__device__ float g_K[NB * NHEAD * NS * DH];
__device__ float g_V[NB * NHEAD * NS * DH];
__device__ float g_ctx[NB * NS * D_MODEL];

// ---------------------------------------------------------------------------
// Tiled fp32 GEMM: C[m,e] = sum_k A[m,k] * W[e,k]   (torch Linear, W row-major [out,in])
// 128x128 block, BK=8, 256 threads, 8x8 per-thread microtile.
// QKV_LAYOUT=true scatters output into [B,H,S,DH]; false writes row-major.
// ---------------------------------------------------------------------------
template <bool QKV_LAYOUT>
__device__ __forceinline__ void gemm_body(const float* __restrict__ A,
                                          const float* __restrict__ W,
                                          float* __restrict__ C)
{
    __shared__ float As[8][128];
    __shared__ float Bs[8][128];

    const int tid = threadIdx.x;
    const int bm = blockIdx.y * 128;
    const int bn = blockIdx.x * 128;
    const int ldr = tid >> 1;            // 0..127
    const int ldc = (tid & 1) << 2;      // 0 or 4
    const int tx = tid & 15;
    const int ty = tid >> 4;

    const float* Ap = A + (size_t)(bm + ldr) * D_MODEL + ldc;
    const float* Wp = W + (size_t)(bn + ldr) * D_MODEL + ldc;

    float acc[8][8];
#pragma unroll
    for (int i = 0; i < 8; i++)
#pragma unroll
        for (int j = 0; j < 8; j++) acc[i][j] = 0.0f;

    for (int k0 = 0; k0 < D_MODEL; k0 += 8) {
        float4 av = *(const float4*)(Ap + k0);
        float4 wv = *(const float4*)(Wp + k0);
        As[ldc + 0][ldr] = av.x; As[ldc + 1][ldr] = av.y;
        As[ldc + 2][ldr] = av.z; As[ldc + 3][ldr] = av.w;
        Bs[ldc + 0][ldr] = wv.x; Bs[ldc + 1][ldr] = wv.y;
        Bs[ldc + 2][ldr] = wv.z; Bs[ldc + 3][ldr] = wv.w;
        __syncthreads();
#pragma unroll
        for (int kk = 0; kk < 8; kk++) {
            float ar[8], br[8];
            *(float4*)(ar)     = *(const float4*)(&As[kk][ty * 8]);
            *(float4*)(ar + 4) = *(const float4*)(&As[kk][ty * 8 + 4]);
            *(float4*)(br)     = *(const float4*)(&Bs[kk][tx * 8]);
            *(float4*)(br + 4) = *(const float4*)(&Bs[kk][tx * 8 + 4]);
#pragma unroll
            for (int i = 0; i < 8; i++)
#pragma unroll
                for (int j = 0; j < 8; j++)
                    acc[i][j] = fmaf(ar[i], br[j], acc[i][j]);
        }
        __syncthreads();
    }

#pragma unroll
    for (int i = 0; i < 8; i++) {
        const int m = bm + ty * 8 + i;
        const int e = bn + tx * 8;
        float4 lo = make_float4(acc[i][0], acc[i][1], acc[i][2], acc[i][3]);
        float4 hi = make_float4(acc[i][4], acc[i][5], acc[i][6], acc[i][7]);
        if (QKV_LAYOUT) {
            // m = b*NS + s ; e = h*DH + dh  ->  [b,h,s,dh]
            const int b = m >> 11;
            const int s = m & (NS - 1);
            const int h = e >> 6;
            const int dh = e & (DH - 1);
            float* dst = C + (((size_t)(b * NHEAD + h) * NS + s) * DH + dh);
            *(float4*)dst = lo;
            *(float4*)(dst + 4) = hi;   // e..e+7 never crosses a 64 (head) boundary
        } else {
            float* dst = C + (size_t)m * D_MODEL + e;
            *(float4*)dst = lo;
            *(float4*)(dst + 4) = hi;
        }
    }
}

__global__ void __launch_bounds__(256) qkv_gemm(const float* __restrict__ X,
                                                const float* __restrict__ Wq,
                                                const float* __restrict__ Wk,
                                                const float* __restrict__ Wv)
{
    const float* W = (blockIdx.z == 0) ? Wq : (blockIdx.z == 1) ? Wk : Wv;
    float* C = (blockIdx.z == 0) ? g_Q : (blockIdx.z == 1) ? g_K : g_V;
    gemm_body<true>(X, W, C);
}

__global__ void __launch_bounds__(256) out_gemm(const float* __restrict__ Wo,
                                                float* __restrict__ out)
{
    gemm_body<false>(g_ctx, Wo, out);
}

// ---------------------------------------------------------------------------
// Flash-style sliding-window attention.
// Block: 64 queries x full 64-dim head. 256 threads, 4x4 microtile.
// Keys valid for query i: j in [0, i + WIN-1] (tril(diagonal=WIN-1)) and mask!=0.
// K^T tile buffer is reused to hold P after scores are consumed (stays <=48KB smem).
// ---------------------------------------------------------------------------
__global__ void __launch_bounds__(256) attn_kernel(const int* __restrict__ amask)
{
    __shared__ float Qs[64][64];   // [dh][row]
    __shared__ float KPs[64][64];  // [dh][col] for K^T, reused as P [row][col]
    __shared__ float Vs[64][64];   // [col][dh]

    const int tid = threadIdx.x;
    const int tx = tid & 15;
    const int ty = tid >> 4;
    const int i0 = blockIdx.x * 64;
    const int h = blockIdx.y;
    const int b = blockIdx.z;

    const size_t base = ((size_t)(b * NHEAD + h)) * NS * DH;
    const float* Qg = g_Q + base;
    const float* Kg = g_K + base;
    const float* Vg = g_V + base;

    // load Q tile, transposed to [dh][row]
    {
        const int r = tid >> 2;
        const int c0 = (tid & 3) * 16;
        const float* qp = Qg + (size_t)(i0 + r) * DH + c0;
#pragma unroll
        for (int u = 0; u < 4; u++) {
            float4 q4 = *(const float4*)(qp + u * 4);
            Qs[c0 + u * 4 + 0][r] = q4.x;
            Qs[c0 + u * 4 + 1][r] = q4.y;
            Qs[c0 + u * 4 + 2][r] = q4.z;
            Qs[c0 + u * 4 + 3][r] = q4.w;
        }
    }

    float Oa[4][4];
    float mrow[4], lrow[4];
#pragma unroll
    for (int i = 0; i < 4; i++) {
        mrow[i] = -1e30f;
        lrow[i] = 0.0f;
#pragma unroll
        for (int j = 0; j < 4; j++) Oa[i][j] = 0.0f;
    }

    const int jmax = min(i0 + 63 + (WIN - 1), NS - 1);

    for (int j0 = 0; j0 <= jmax; j0 += 64) {
        // load K (transposed) + V (natural)
        {
            const int c = tid >> 2;
            const int d0 = (tid & 3) * 16;
            const float* kp = Kg + (size_t)(j0 + c) * DH + d0;
            const float* vp = Vg + (size_t)(j0 + c) * DH + d0;
#pragma unroll
            for (int u = 0; u < 4; u++) {
                float4 k4 = *(const float4*)(kp + u * 4);
                KPs[d0 + u * 4 + 0][c] = k4.x;
                KPs[d0 + u * 4 + 1][c] = k4.y;
                KPs[d0 + u * 4 + 2][c] = k4.z;
                KPs[d0 + u * 4 + 3][c] = k4.w;
                *(float4*)(&Vs[c][d0 + u * 4]) = *(const float4*)(vp + u * 4);
            }
        }
        __syncthreads();

        // scores: S[4x4] = Q_rows . K_cols
        float Sc[4][4];
#pragma unroll
        for (int i = 0; i < 4; i++)
#pragma unroll
            for (int j = 0; j < 4; j++) Sc[i][j] = 0.0f;

#pragma unroll 16
        for (int kk = 0; kk < 64; kk++) {
            float4 q4 = *(const float4*)(&Qs[kk][ty * 4]);
            float4 k4 = *(const float4*)(&KPs[kk][tx * 4]);
            float qa[4] = {q4.x, q4.y, q4.z, q4.w};
            float ka[4] = {k4.x, k4.y, k4.z, k4.w};
#pragma unroll
            for (int i = 0; i < 4; i++)
#pragma unroll
                for (int j = 0; j < 4; j++)
                    Sc[i][j] = fmaf(qa[i], ka[j], Sc[i][j]);
        }
        __syncthreads();  // K^T reads complete before KPs is reused as P

        // mask + scale + online softmax
        float madd[4];
#pragma unroll
        for (int j = 0; j < 4; j++)
            madd[j] = (amask[b * NS + j0 + tx * 4 + j] != 0) ? 0.0f : -1e30f;

#pragma unroll
        for (int i = 0; i < 4; i++) {
            const int ig = i0 + ty * 4 + i;
            float bmax = -1e30f;
#pragma unroll
            for (int j = 0; j < 4; j++) {
                const int jg = j0 + tx * 4 + j;
                float s = Sc[i][j] * 0.125f + madd[j];   // 1/sqrt(64)
                if (jg - ig > (WIN - 1)) s = -1e30f;
                Sc[i][j] = s;
                bmax = fmaxf(bmax, s);
            }
#pragma unroll
            for (int off = 8; off >= 1; off >>= 1)
                bmax = fmaxf(bmax, __shfl_xor_sync(0xffffffffu, bmax, off, 16));

            const float mnew = fmaxf(mrow[i], bmax);
            const float alpha = __expf(mrow[i] - mnew);
            float rsum = 0.0f;
#pragma unroll
            for (int j = 0; j < 4; j++) {
                const float p = __expf(Sc[i][j] - mnew);
                Sc[i][j] = p;
                rsum += p;
            }
#pragma unroll
            for (int off = 8; off >= 1; off >>= 1)
                rsum += __shfl_xor_sync(0xffffffffu, rsum, off, 16);

            lrow[i] = lrow[i] * alpha + rsum;
            mrow[i] = mnew;
#pragma unroll
            for (int j = 0; j < 4; j++) Oa[i][j] *= alpha;
        }

        // P -> shared (reuse KPs as row-major [64][64])
        float* Ps = &KPs[0][0];
#pragma unroll
        for (int i = 0; i < 4; i++)
#pragma unroll
            for (int j = 0; j < 4; j++)
                Ps[(ty * 4 + i) * 64 + tx * 4 + j] = Sc[i][j];
        __syncthreads();

        // O += P @ V
#pragma unroll 16
        for (int j = 0; j < 64; j++) {
            float4 v4 = *(const float4*)(&Vs[j][tx * 4]);
            float va[4] = {v4.x, v4.y, v4.z, v4.w};
#pragma unroll
            for (int i = 0; i < 4; i++) {
                const float p = Ps[(ty * 4 + i) * 64 + j];
#pragma unroll
                for (int c = 0; c < 4; c++)
                    Oa[i][c] = fmaf(p, va[c], Oa[i][c]);
            }
        }
        __syncthreads();
    }

    // finalize: divide by l, write ctx[b, s, h*64 + dh]
#pragma unroll
    for (int i = 0; i < 4; i++) {
        const float inv = 1.0f / lrow[i];
        const int s = i0 + ty * 4 + i;
        float* dst = g_ctx + ((size_t)b * NS + s) * D_MODEL + h * DH + tx * 4;
        float4 o = make_float4(Oa[i][0] * inv, Oa[i][1] * inv,
                               Oa[i][2] * inv, Oa[i][3] * inv);
        *(float4*)dst = o;
    }
}

// ---------------------------------------------------------------------------
extern "C" void kernel_launch(void* const* d_in, const int* in_sizes, int n_in,
                              void* d_out, int out_size)
{
    const float* hidden = (const float*)d_in[0];
    const int* amask    = (const int*)d_in[1];
    const float* Wq     = (const float*)d_in[2];
    const float* Wk     = (const float*)d_in[3];
    const float* Wv     = (const float*)d_in[4];
    const float* Wo     = (const float*)d_in[5];
    float* out = (float*)d_out;

    dim3 gq(D_MODEL / 128, (NB * NS) / 128, 3);
    qkv_gemm<<<gq, 256>>>(hidden, Wq, Wk, Wv);

    dim3 ga(NS / 64, NHEAD, NB);
    attn_kernel<<<ga, 256>>>(amask);

    dim3 go(D_MODEL / 128, (NB * NS) / 128, 1);
    out_gemm<<<go, 256>>>(Wo, out);
}

// round 3
// speedup vs baseline: 3.1986x; 3.1986x over previous
#include <cuda_runtime.h>
#include <cuda_bf16.h>
#include <cstdint>

#define D_MODEL 1024
#define NHEAD 16
#define DH 64
#define WIN 256
#define NB 2
#define NS 2048
#define MROWS (NB * NS)   // 4096

typedef __nv_bfloat16 bf16;

// ---------------- device scratch (allocation-free rule) ----------------
__device__ bf16 g_Ahi[MROWS * D_MODEL];
__device__ bf16 g_Alo[MROWS * D_MODEL];
__device__ bf16 g_Whi[4096 * D_MODEL];     // [Wq;Wk;Wv;Wo]
__device__ bf16 g_Wlo[4096 * D_MODEL];
__device__ bf16 g_Qhi[MROWS * D_MODEL];    // [b,h,s,d]
__device__ bf16 g_Qlo[MROWS * D_MODEL];
__device__ bf16 g_Khi[MROWS * D_MODEL];
__device__ bf16 g_Klo[MROWS * D_MODEL];
__device__ bf16 g_Vhi[MROWS * D_MODEL];
__device__ bf16 g_Vlo[MROWS * D_MODEL];
__device__ bf16 g_Chi[MROWS * D_MODEL];    // attention ctx, [b,s,e]
__device__ bf16 g_Clo[MROWS * D_MODEL];

// ---------------- helpers (all baseline PTX, sm_80+) ----------------
__device__ __forceinline__ uint32_t smem_u32(const void* p) {
    uint32_t a;
    asm("{ .reg .u64 t; cvta.to.shared.u64 t, %1; cvt.u32.u64 %0, t; }" : "=r"(a) : "l"(p));
    return a;
}
__device__ __forceinline__ void cp16(uint32_t s, const void* g) {
    asm volatile("cp.async.cg.shared.global [%0], [%1], 16;" :: "r"(s), "l"(g));
}
#define CP_COMMIT() asm volatile("cp.async.commit_group;" ::: "memory")
#define CP_WAIT0()  asm volatile("cp.async.wait_group 0;" ::: "memory")

__device__ __forceinline__ void ldsm4(uint32_t* r, uint32_t a) {
    asm volatile("ldmatrix.sync.aligned.m8n8.x4.shared.b16 {%0,%1,%2,%3}, [%4];"
        : "=r"(r[0]), "=r"(r[1]), "=r"(r[2]), "=r"(r[3]) : "r"(a));
}
__device__ __forceinline__ void ldsm4t(uint32_t* r, uint32_t a) {
    asm volatile("ldmatrix.sync.aligned.m8n8.x4.trans.shared.b16 {%0,%1,%2,%3}, [%4];"
        : "=r"(r[0]), "=r"(r[1]), "=r"(r[2]), "=r"(r[3]) : "r"(a));
}
__device__ __forceinline__ void mma16816(float* c, const uint32_t* a, const uint32_t* b) {
    asm volatile("mma.sync.aligned.m16n8k16.row.col.f32.bf16.bf16.f32 "
        "{%0,%1,%2,%3}, {%4,%5,%6,%7}, {%8,%9}, {%0,%1,%2,%3};"
        : "+f"(c[0]), "+f"(c[1]), "+f"(c[2]), "+f"(c[3])
        : "r"(a[0]), "r"(a[1]), "r"(a[2]), "r"(a[3]), "r"(b[0]), "r"(b[1]));
}

// split two f32 into bf16x2 hi + bf16x2 lo (x0 in low half)
__device__ __forceinline__ void split_pack2(float x0, float x1, uint32_t& hi, uint32_t& lo) {
    __nv_bfloat162 h = __float22bfloat162_rn(make_float2(x0, x1));
    float h0 = __bfloat162float(h.x), h1 = __bfloat162float(h.y);
    __nv_bfloat162 l = __float22bfloat162_rn(make_float2(x0 - h0, x1 - h1));
    hi = *(uint32_t*)&h;
    lo = *(uint32_t*)&l;
}

// ---------------- convert f32 -> bf16 hi/lo (X and stacked weights) ----------------
__global__ void __launch_bounds__(256) convert_all(const float* __restrict__ X,
                                                   const float* __restrict__ Wq,
                                                   const float* __restrict__ Wk,
                                                   const float* __restrict__ Wv,
                                                   const float* __restrict__ Wo)
{
    const size_t NA4 = (size_t)MROWS * D_MODEL / 4;
    size_t i4 = (size_t)blockIdx.x * blockDim.x + threadIdx.x;
    const float* src;
    bf16 *dh, *dl;
    size_t off;
    if (i4 < NA4) {
        off = i4 * 4;
        src = X + off;
        dh = g_Ahi; dl = g_Alo;
    } else {
        size_t j = (i4 - NA4) * 4;
        off = j;
        int row = (int)(j >> 10);
        int col = (int)(j & 1023);
        const float* W = (row < 1024) ? Wq : (row < 2048) ? Wk : (row < 3072) ? Wv : Wo;
        src = W + (size_t)(row & 1023) * D_MODEL + col;
        dh = g_Whi; dl = g_Wlo;
    }
    float4 v = *(const float4*)src;
    uint32_t h0, l0, h1, l1;
    split_pack2(v.x, v.y, h0, l0);
    split_pack2(v.z, v.w, h1, l1);
    *(uint2*)(dh + off) = make_uint2(h0, h1);
    *(uint2*)(dl + off) = make_uint2(l0, l1);
}

// ---------------- mma GEMM: C[m,n] = sum_k A[m,k] * W[n,k] ----------------
// 128x128x32 tiles, 8 warps (warp tile 64x32), cp.async double buffer.
// mode 0: scatter bf16 hi/lo into Q/K/V [b,h,s,d]; mode 1: f32 to out.
#define SROW 40                 // 32 + 8 pad (bf16 elems per smem row)
#define MAT_ELEMS (128 * SROW)  // 5120
#define STAGE_ELEMS (4 * MAT_ELEMS)
#define GEMM_SMEM (2 * STAGE_ELEMS * 2)  // bytes = 81920

__global__ void __launch_bounds__(256) gemm_mma(const bf16* __restrict__ Ahi,
                                                const bf16* __restrict__ Alo,
                                                int wrow0, int mode,
                                                float* __restrict__ out)
{
    extern __shared__ bf16 sm[];
    const int tid = threadIdx.x, lane = tid & 31, wid = tid >> 5;
    const int bm = blockIdx.y * 128, bn = blockIdx.x * 128;
    const bf16* Whi = g_Whi + (size_t)wrow0 * D_MODEL;
    const bf16* Wlo = g_Wlo + (size_t)wrow0 * D_MODEL;
    const uint32_t sbase = smem_u32(sm);

    float acc[4][4][4];
#pragma unroll
    for (int i = 0; i < 4; i++)
#pragma unroll
        for (int j = 0; j < 4; j++)
#pragma unroll
            for (int k = 0; k < 4; k++) acc[i][j][k] = 0.0f;

    const int wm = (wid & 1) * 64, wn = (wid >> 1) * 32;
    const int tg = lane & 3, rg = lane >> 2;

    // stage-0 loads
    {
#pragma unroll
        for (int m = 0; m < 4; m++) {
            const bf16* src = (m == 0) ? Ahi : (m == 1) ? Alo : (m == 2) ? Whi : Wlo;
            const int row0 = (m < 2) ? bm : bn;
#pragma unroll
            for (int r = 0; r < 2; r++) {
                int c = tid + r * 256;
                int row = c >> 2, cc = c & 3;
                cp16(sbase + (uint32_t)(m * MAT_ELEMS + row * SROW + cc * 8) * 2,
                     src + (size_t)(row0 + row) * D_MODEL + cc * 8);
            }
        }
        CP_COMMIT();
    }

    for (int kt = 0; kt < 32; kt++) {
        const int buf = kt & 1;
        CP_WAIT0();
        __syncthreads();
        if (kt + 1 < 32) {
            const int k0 = (kt + 1) * 32;
            const int nb = buf ^ 1;
#pragma unroll
            for (int m = 0; m < 4; m++) {
                const bf16* src = (m == 0) ? Ahi : (m == 1) ? Alo : (m == 2) ? Whi : Wlo;
                const int row0 = (m < 2) ? bm : bn;
#pragma unroll
                for (int r = 0; r < 2; r++) {
                    int c = tid + r * 256;
                    int row = c >> 2, cc = c & 3;
                    cp16(sbase + (uint32_t)(nb * STAGE_ELEMS + m * MAT_ELEMS + row * SROW + cc * 8) * 2,
                         src + (size_t)(row0 + row) * D_MODEL + k0 + cc * 8);
                }
            }
            CP_COMMIT();
        }
        const uint32_t sA = sbase + (uint32_t)(buf * STAGE_ELEMS) * 2;
#pragma unroll
        for (int kk = 0; kk < 32; kk += 16) {
            uint32_t ah[4][4], al[4][4];
#pragma unroll
            for (int mi = 0; mi < 4; mi++) {
                uint32_t ad = sA + (uint32_t)((wm + mi * 16 + (lane & 15)) * SROW + kk + (lane >> 4) * 8) * 2;
                ldsm4(ah[mi], ad);
                ldsm4(al[mi], ad + MAT_ELEMS * 2);
            }
            uint32_t bh[4][2], bl[4][2];
            const int g4 = lane >> 3;
#pragma unroll
            for (int np = 0; np < 4; np += 2) {
                uint32_t bd = sA + (uint32_t)(2 * MAT_ELEMS +
                    (wn + (np + (g4 >> 1)) * 8 + (lane & 7)) * SROW + kk + (g4 & 1) * 8) * 2;
                uint32_t t[4];
                ldsm4(t, bd);
                bh[np][0] = t[0]; bh[np][1] = t[1]; bh[np + 1][0] = t[2]; bh[np + 1][1] = t[3];
                ldsm4(t, bd + MAT_ELEMS * 2);
                bl[np][0] = t[0]; bl[np][1] = t[1]; bl[np + 1][0] = t[2]; bl[np + 1][1] = t[3];
            }
#pragma unroll
            for (int mi = 0; mi < 4; mi++)
#pragma unroll
                for (int ni = 0; ni < 4; ni++) {
                    mma16816(acc[mi][ni], ah[mi], bh[ni]);
                    mma16816(acc[mi][ni], ah[mi], bl[ni]);
                    mma16816(acc[mi][ni], al[mi], bh[ni]);
                }
        }
        __syncthreads();
    }

    // epilogue
#pragma unroll
    for (int mi = 0; mi < 4; mi++) {
        const int mrow0 = bm + wm + mi * 16 + rg;
#pragma unroll
        for (int ni = 0; ni < 4; ni++) {
            const int ngl = bn + wn + ni * 8 + tg * 2;
#pragma unroll
            for (int r = 0; r < 2; r++) {
                const int m = mrow0 + r * 8;
                const float x0 = acc[mi][ni][r * 2], x1 = acc[mi][ni][r * 2 + 1];
                if (mode == 0) {
                    const int mat = ngl >> 10, e = ngl & 1023, hh = e >> 6, dd = e & 63;
                    const int bb = m >> 11, ss = m & (NS - 1);
                    const size_t off = ((size_t)(bb * NHEAD + hh) * NS + ss) * DH + dd;
                    uint32_t hi, lo;
                    split_pack2(x0, x1, hi, lo);
                    bf16 *ph, *pl;
                    if (mat == 0)      { ph = g_Qhi; pl = g_Qlo; }
                    else if (mat == 1) { ph = g_Khi; pl = g_Klo; }
                    else               { ph = g_Vhi; pl = g_Vlo; }
                    *(uint32_t*)(ph + off) = hi;
                    *(uint32_t*)(pl + off) = lo;
                } else {
                    *(float2*)(out + (size_t)m * D_MODEL + ngl) = make_float2(x0, x1);
                }
            }
        }
    }
}

// ---------------- mma flash attention: 64q x 64k tiles, 4 warps ----------------
#define KROW 72   // 64 + 8 pad
__global__ void __launch_bounds__(128) attn_mma(const int* __restrict__ amask)
{
    __shared__ bf16 sKh[64][KROW], sKl[64][KROW], sVh[64][KROW], sVl[64][KROW];
    __shared__ float smask[64];

    const int tid = threadIdx.x, lane = tid & 31, wid = tid >> 5;
    const int tg = lane & 3, rg = lane >> 2;
    const int i0 = blockIdx.x * 64, h = blockIdx.y, b = blockIdx.z;
    const size_t base = ((size_t)(b * NHEAD + h)) * NS * DH;

    const uint32_t skh = smem_u32(&sKh[0][0]);
    const uint32_t skl = smem_u32(&sKl[0][0]);
    const uint32_t svh = smem_u32(&sVh[0][0]);
    const uint32_t svl = smem_u32(&sVl[0][0]);

    // ---- stage Q through sKh/sKl, ldmatrix into registers ----
#pragma unroll
    for (int i = 0; i < 4; i++) {
        int c = tid + i * 128;
        int row = c >> 3, cc = c & 7;
        const size_t g = base + (size_t)(i0 + row) * DH + cc * 8;
        const uint32_t so = (uint32_t)(row * KROW + cc * 8) * 2;
        cp16(skh + so, g_Qhi + g);
        cp16(skl + so, g_Qlo + g);
    }
    CP_COMMIT();
    CP_WAIT0();
    __syncthreads();

    const int m0 = wid * 16;
    uint32_t qh[4][4], ql[4][4];
#pragma unroll
    for (int u = 0; u < 4; u++) {
        const uint32_t off = (uint32_t)((m0 + (lane & 15)) * KROW + u * 16 + (lane >> 4) * 8) * 2;
        ldsm4(qh[u], skh + off);
        ldsm4(ql[u], skl + off);
    }
    __syncthreads();

    float o[8][4];
#pragma unroll
    for (int i = 0; i < 8; i++)
#pragma unroll
        for (int j = 0; j < 4; j++) o[i][j] = 0.0f;
    float mrow[2] = {-1e30f, -1e30f}, lrow[2] = {0.0f, 0.0f};

    const int jlast = min(i0 + 63 + (WIN - 1), NS - 1) >> 6;
    for (int t = 0; t <= jlast; t++) {
        const int j0 = t * 64;
#pragma unroll
        for (int i = 0; i < 4; i++) {
            int c = tid + i * 128;
            int row = c >> 3, cc = c & 7;
            const size_t g = base + (size_t)(j0 + row) * DH + cc * 8;
            const uint32_t so = (uint32_t)(row * KROW + cc * 8) * 2;
            cp16(skh + so, g_Khi + g);
            cp16(skl + so, g_Klo + g);
            cp16(svh + so, g_Vhi + g);
            cp16(svl + so, g_Vlo + g);
        }
        if (tid < 64) smask[tid] = (amask[b * NS + j0 + tid] != 0) ? 0.0f : -1e30f;
        CP_COMMIT();
        CP_WAIT0();
        __syncthreads();

        // ---- S = Q K^T ----
        float sc[8][4];
#pragma unroll
        for (int i = 0; i < 8; i++)
#pragma unroll
            for (int j = 0; j < 4; j++) sc[i][j] = 0.0f;

        const int g4 = lane >> 3;
#pragma unroll
        for (int u = 0; u < 4; u++) {
#pragma unroll
            for (int np = 0; np < 8; np += 2) {
                const uint32_t bd = (uint32_t)(((np + (g4 >> 1)) * 8 + (lane & 7)) * KROW
                                               + u * 16 + (g4 & 1) * 8) * 2;
                uint32_t th[4], tl[4];
                ldsm4(th, skh + bd);
                ldsm4(tl, skl + bd);
                mma16816(sc[np], qh[u], &th[0]);
                mma16816(sc[np], qh[u], &tl[0]);
                mma16816(sc[np], ql[u], &th[0]);
                mma16816(sc[np + 1], qh[u], &th[2]);
                mma16816(sc[np + 1], qh[u], &tl[2]);
                mma16816(sc[np + 1], ql[u], &th[2]);
            }
        }

        // ---- mask + online softmax ----
        float mk[16];
#pragma unroll
        for (int nt = 0; nt < 8; nt++) {
            mk[nt * 2 + 0] = smask[nt * 8 + tg * 2 + 0];
            mk[nt * 2 + 1] = smask[nt * 8 + tg * 2 + 1];
        }
#pragma unroll
        for (int r = 0; r < 2; r++) {
            const int ig = i0 + m0 + rg + r * 8;
            float rmax = -1e30f;
#pragma unroll
            for (int nt = 0; nt < 8; nt++)
#pragma unroll
                for (int e = 0; e < 2; e++) {
                    const int jg = j0 + nt * 8 + tg * 2 + e;
                    float s = sc[nt][r * 2 + e] * 0.125f + mk[nt * 2 + e];
                    if (jg - ig > (WIN - 1)) s = -1e30f;
                    sc[nt][r * 2 + e] = s;
                    rmax = fmaxf(rmax, s);
                }
            rmax = fmaxf(rmax, __shfl_xor_sync(0xffffffffu, rmax, 1));
            rmax = fmaxf(rmax, __shfl_xor_sync(0xffffffffu, rmax, 2));
            const float mnew = fmaxf(mrow[r], rmax);
            const float alpha = __expf(mrow[r] - mnew);
            float rsum = 0.0f;
#pragma unroll
            for (int nt = 0; nt < 8; nt++)
#pragma unroll
                for (int e = 0; e < 2; e++) {
                    const float p = __expf(sc[nt][r * 2 + e] - mnew);
                    sc[nt][r * 2 + e] = p;
                    rsum += p;
                }
            rsum += __shfl_xor_sync(0xffffffffu, rsum, 1);
            rsum += __shfl_xor_sync(0xffffffffu, rsum, 2);
            lrow[r] = lrow[r] * alpha + rsum;
            mrow[r] = mnew;
#pragma unroll
            for (int nt = 0; nt < 8; nt++) {
                o[nt][r * 2 + 0] *= alpha;
                o[nt][r * 2 + 1] *= alpha;
            }
        }

        // ---- P fragments (in-register repack, FA2 style) ----
        uint32_t ph[4][4], pl[4][4];
#pragma unroll
        for (int u = 0; u < 4; u++) {
            split_pack2(sc[2 * u][0],     sc[2 * u][1],     ph[u][0], pl[u][0]);
            split_pack2(sc[2 * u][2],     sc[2 * u][3],     ph[u][1], pl[u][1]);
            split_pack2(sc[2 * u + 1][0], sc[2 * u + 1][1], ph[u][2], pl[u][2]);
            split_pack2(sc[2 * u + 1][2], sc[2 * u + 1][3], ph[u][3], pl[u][3]);
        }

        // ---- O += P V ----
#pragma unroll
        for (int u = 0; u < 4; u++) {
#pragma unroll
            for (int np = 0; np < 8; np += 2) {
                const uint32_t bd = (uint32_t)((u * 16 + (g4 & 1) * 8 + (lane & 7)) * KROW
                                               + (np + (g4 >> 1)) * 8) * 2;
                uint32_t th[4], tl[4];
                ldsm4t(th, svh + bd);
                ldsm4t(tl, svl + bd);
                mma16816(o[np], ph[u], &th[0]);
                mma16816(o[np], ph[u], &tl[0]);
                mma16816(o[np], pl[u], &th[0]);
                mma16816(o[np + 1], ph[u], &th[2]);
                mma16816(o[np + 1], ph[u], &tl[2]);
                mma16816(o[np + 1], pl[u], &th[2]);
            }
        }
        __syncthreads();
    }

    // ---- epilogue: ctx as bf16 hi/lo [b,s,e] ----
#pragma unroll
    for (int r = 0; r < 2; r++) {
        const float inv = 1.0f / lrow[r];
        const int s_g = i0 + m0 + rg + r * 8;
        const size_t rowoff = ((size_t)b * NS + s_g) * D_MODEL + h * DH;
#pragma unroll
        for (int nt = 0; nt < 8; nt++) {
            uint32_t hi, lo;
            split_pack2(o[nt][r * 2] * inv, o[nt][r * 2 + 1] * inv, hi, lo);
            const size_t off = rowoff + nt * 8 + tg * 2;
            *(uint32_t*)(g_Chi + off) = hi;
            *(uint32_t*)(g_Clo + off) = lo;
        }
    }
}

// ---------------- host launcher ----------------
extern "C" void kernel_launch(void* const* d_in, const int* in_sizes, int n_in,
                              void* d_out, int out_size)
{
    const float* hidden = (const float*)d_in[0];
    const int* amask    = (const int*)d_in[1];
    const float* Wq     = (const float*)d_in[2];
    const float* Wk     = (const float*)d_in[3];
    const float* Wv     = (const float*)d_in[4];
    const float* Wo     = (const float*)d_in[5];
    float* out = (float*)d_out;

    static int smem_set = 0;
    if (!smem_set) {
        cudaFuncSetAttribute(gemm_mma, cudaFuncAttributeMaxDynamicSharedMemorySize, GEMM_SMEM);
        smem_set = 1;
    }

    bf16 *pAhi, *pAlo, *pChi, *pClo;
    cudaGetSymbolAddress((void**)&pAhi, g_Ahi);
    cudaGetSymbolAddress((void**)&pAlo, g_Alo);
    cudaGetSymbolAddress((void**)&pChi, g_Chi);
    cudaGetSymbolAddress((void**)&pClo, g_Clo);

    // 1. f32 -> bf16 hi/lo (X + stacked weights)
    convert_all<<<2 * (MROWS * D_MODEL / 4) / 256, 256>>>(hidden, Wq, Wk, Wv, Wo);

    // 2. fused QKV projection (N = 3072), scatter bf16 Q/K/V
    gemm_mma<<<dim3(3 * D_MODEL / 128, MROWS / 128), 256, GEMM_SMEM>>>(pAhi, pAlo, 0, 0, nullptr);

    // 3. attention
    attn_mma<<<dim3(NS / 64, NHEAD, NB), 128>>>(amask);

    // 4. output projection (weight rows 3072..4095), f32 out
    gemm_mma<<<dim3(D_MODEL / 128, MROWS / 128), 256, GEMM_SMEM>>>(pChi, pClo, 3 * D_MODEL, 1, out);
}